// round 15
// baseline (speedup 1.0000x reference)
#include <cuda_runtime.h>
#include <math.h>

#define DD 96
#define LL 9216
#define KK 4
#define NN 16
#define RR 6
#define CC 38
#define LC 16
#define NC 576   // LL/LC
#define KD 384   // KK*DD
#define LOG2E 1.4426950408889634f
#define LN2   0.6931471805599453f

typedef unsigned long long u64;

__device__ __forceinline__ float ex2f(float x){
    float y; asm("ex2.approx.f32 %0, %1;" : "=f"(y) : "f"(x)); return y;
}
__device__ __forceinline__ float lg2f(float x){
    float y; asm("lg2.approx.f32 %0, %1;" : "=f"(y) : "f"(x)); return y;
}
// packed f32x2 helpers (sm_100+)
__device__ __forceinline__ u64 pack2(float lo, float hi){
    u64 r; asm("mov.b64 %0, {%1,%2};" : "=l"(r) : "f"(lo), "f"(hi)); return r;
}
__device__ __forceinline__ void unpack2(u64 v, float& lo, float& hi){
    asm("mov.b64 {%0,%1}, %2;" : "=f"(lo), "=f"(hi) : "l"(v));
}
__device__ __forceinline__ u64 mul2(u64 a, u64 b){
    u64 r; asm("mul.rn.f32x2 %0, %1, %2;" : "=l"(r) : "l"(a), "l"(b)); return r;
}
__device__ __forceinline__ u64 fma2(u64 a, u64 b, u64 c){
    u64 r; asm("fma.rn.f32x2 %0, %1, %2, %3;" : "=l"(r) : "l"(a), "l"(b), "l"(c)); return r;
}
__device__ __forceinline__ u64 add2(u64 a, u64 b){
    u64 r; asm("add.rn.f32x2 %0, %1, %2;" : "=l"(r) : "l"(a), "l"(b)); return r;
}
__device__ __forceinline__ float softplusf(float x){
    if (x > 20.f) return x;
    float t = ex2f(x * LOG2E);            // e^x
    return lg2f(1.f + t) * LN2;           // ln(1+e^x)
}

// scratch (no allocations allowed)
__device__ float  g_xT[DD*LL];          // transposed image per d
__device__ float  g_BC[KK*LL*16];       // (k,l,[C0..15])  (C only)
__device__ float2 g_dx[KK*LL*DD];       // (k,l,d) -> (S_cum, y_local + x*Ds)
__device__ float  g_Sd[KD*NC];          // [kd][ch]
__device__ float  g_H [KD*NC*NN];       // [kd][ch][n] chunk h (pass1) then h_in (pass2)
__device__ float  g_y [KK*LL*DD];       // 4 planes, aligned to output index l

// ---------------------------------------------------------------------------
// Kernel T: per-d HW transpose of x
// ---------------------------------------------------------------------------
__global__ void k_transpose(const float* __restrict__ x){
    __shared__ float tile[32][33];
    int d  = blockIdx.z;
    int h0 = blockIdx.x*32, w0 = blockIdx.y*32;
    int tx = threadIdx.x,  ty = threadIdx.y;
    const float* xp = x    + (size_t)d*LL;
    float*       op = g_xT + (size_t)d*LL;
    #pragma unroll
    for (int i=0;i<4;i++) tile[ty+8*i][tx] = xp[(h0+ty+8*i)*96 + w0+tx];
    __syncthreads();
    #pragma unroll
    for (int i=0;i<4;i++) op[(w0+ty+8*i)*96 + h0+tx] = tile[tx][ty+8*i];
}

// ---------------------------------------------------------------------------
// Kernel A (fused): projections + chunk-local scan (f32x2) with local output.
// ---------------------------------------------------------------------------
__global__ __launch_bounds__(384) void k_proj(
    const float* __restrict__ x,  const float* __restrict__ W,
    const float* __restrict__ dtw,const float* __restrict__ dtb,
    const float* __restrict__ A_logs, const float* __restrict__ Ds)
{
    __shared__ float xs_s [96*33];
    __shared__ float Wt_s [96*40];   // reused as delta_s after GEMM
    __shared__ float dbl_s[40*33];
    __shared__ float Wdt_s[96*6];
    __shared__ float bias_s[96];

    int k   = blockIdx.y;
    int l0  = blockIdx.x*32;
    int tid = threadIdx.x;
    const float* src = (k & 1) ? g_xT : x;

    for (int idx=tid; idx<96*32; idx+=384){
        int d = idx>>5, li = idx&31;
        int l = l0+li;
        int ls = (k<2) ? l : (LL-1-l);
        xs_s[d*33+li] = src[(size_t)d*LL + ls];
    }
    for (int idx=tid; idx<CC*96; idx+=384){
        int c = idx/96, d = idx - c*96;
        Wt_s[d*40+c] = W[(k*CC+c)*96 + d];
    }
    for (int idx=tid; idx<96*6; idx+=384) Wdt_s[idx] = dtw[k*576 + idx];
    if (tid < 96) bias_s[tid] = dtb[k*96 + tid];
    __syncthreads();

    int lane = tid & 31, wrp = tid >> 5;
    if (wrp < 10){
        int c0 = wrp*4;
        float ax=0.f, ay=0.f, az=0.f, aw=0.f;
        for (int d=0; d<96; d++){
            float  xv = xs_s[d*33+lane];
            float4 wv = *(const float4*)&Wt_s[d*40+c0];
            ax = fmaf(wv.x, xv, ax); ay = fmaf(wv.y, xv, ay);
            az = fmaf(wv.z, xv, az); aw = fmaf(wv.w, xv, aw);
        }
        dbl_s[(c0+0)*33+lane] = ax;
        dbl_s[(c0+1)*33+lane] = ay;
        dbl_s[(c0+2)*33+lane] = az;
        dbl_s[(c0+3)*33+lane] = aw;
    }
    __syncthreads();   // GEMM done; Wt_s dead -> reuse as delta_s

    float* delta_s = Wt_s;

    // C out (c in [22,38) of dbl)
    for (int idx=tid; idx<32*16; idx+=384){
        int li = idx>>4, j = idx&15;
        g_BC[((size_t)k*LL + l0+li)*16 + j] = dbl_s[(22+j)*33 + li];
    }
    // delta (fast softplus)
    for (int idx=tid; idx<96*32; idx+=384){
        int d = idx%96, li = idx/96;
        float acc = bias_s[d];
        #pragma unroll
        for (int r=0; r<6; r++) acc = fmaf(dbl_s[r*33+li], Wdt_s[d*6+r], acc);
        delta_s[d*33+li] = softplusf(acc);
    }
    __syncthreads();

    // fused chunk-local scan (f32x2), n-split
    {
        int sub = tid / 192;
        int r   = tid - sub*192;
        int d   = r >> 1;
        int nh  = r & 1;
        int kd  = k*96 + d;
        int ch  = blockIdx.x*2 + sub;
        int lb  = sub*16;
        int nb  = nh*8;

        float Aa2[8];
        #pragma unroll
        for (int j=0;j<8;j++) Aa2[j] = -__expf(A_logs[kd*NN + nb + j]) * LOG2E;
        u64 Ap[4];
        #pragma unroll
        for (int p=0;p<4;p++) Ap[p] = pack2(Aa2[2*p], Aa2[2*p+1]);
        u64 Hp[4];
        #pragma unroll
        for (int p=0;p<4;p++) Hp[p] = pack2(0.f, 0.f);
        float sd = 0.f;
        float Dsv = Ds[kd];
        float2* dxw = g_dx + ((size_t)k*LL + l0 + lb)*96 + d;

        #pragma unroll
        for (int i=0; i<LC; i++){
            int li = lb + i;
            float delta = delta_s[d*33+li];
            float xv    = xs_s[d*33+li];
            float du    = delta * xv;
            sd += delta;
            u64 Dp  = pack2(delta, delta);
            u64 DUp = pack2(du, du);
            u64 Cp[4];
            #pragma unroll
            for (int p=0; p<4; p++){
                u64 t = mul2(Dp, Ap[p]);
                float a, b; unpack2(t, a, b);
                u64 e = pack2(ex2f(a), ex2f(b));
                u64 Bp = pack2(dbl_s[(6+nb+2*p)*33+li], dbl_s[(6+nb+2*p+1)*33+li]);
                Hp[p] = fma2(Hp[p], e, mul2(DUp, Bp));
                Cp[p] = pack2(dbl_s[(22+nb+2*p)*33+li], dbl_s[(22+nb+2*p+1)*33+li]);
            }
            u64 Ya = mul2(Hp[0], Cp[0]); Ya = fma2(Hp[1], Cp[1], Ya);
            u64 Yb = mul2(Hp[2], Cp[2]); Yb = fma2(Hp[3], Cp[3], Yb);
            u64 Ys = add2(Ya, Yb);
            float ya, yb; unpack2(Ys, ya, yb);
            float y = ya + yb;
            y += __shfl_xor_sync(0xffffffffu, y, 1);
            if (nh == 0) dxw[(size_t)i*96] = make_float2(sd, y + xv*Dsv);
        }
        if (nh == 0) g_Sd[(size_t)kd*NC + ch] = sd;
        float h0,h1,h2,h3,h4,h5,h6,h7;
        unpack2(Hp[0],h0,h1); unpack2(Hp[1],h2,h3);
        unpack2(Hp[2],h4,h5); unpack2(Hp[3],h6,h7);
        float4* hp = (float4*)&g_H[((size_t)kd*NC + ch)*16 + nb];
        hp[0] = make_float4(h0,h1,h2,h3);
        hp[1] = make_float4(h4,h5,h6,h7);
    }
}

// ---------------------------------------------------------------------------
// Pass 2: parallel chunk-combine. One block per (k,d) sequence.
// ---------------------------------------------------------------------------
#define CPT 18
__global__ __launch_bounds__(512) void k_scan2(const float* __restrict__ A_logs){
    __shared__ float sH [NC*17];
    __shared__ float sSd[NC];

    int kd  = blockIdx.x;
    int tid = threadIdx.x;

    const float4* src4 = (const float4*)(g_H + (size_t)kd*NC*16);
    for (int i=tid; i<NC*4; i+=512){
        float4 v = src4[i];
        int e = i*4; int ch = e>>4, n = e&15;
        float* p = &sH[ch*17+n];
        p[0]=v.x; p[1]=v.y; p[2]=v.z; p[3]=v.w;
    }
    const float4* sd4 = (const float4*)(g_Sd + (size_t)kd*NC);
    for (int i=tid; i<NC/4; i+=512){
        float4 v = sd4[i];
        sSd[i*4+0]=v.x; sSd[i*4+1]=v.y; sSd[i*4+2]=v.z; sSd[i*4+3]=v.w;
    }
    __syncthreads();

    int n = tid >> 5;
    int g = tid & 31;
    float Av2 = -__expf(A_logs[kd*16 + n]) * LOG2E;
    int ch0 = g*CPT;

    float Pv[CPT];
    float a = 1.f, b = 0.f;
    #pragma unroll
    for (int j=0; j<CPT; j++){
        float P = ex2f(Av2 * sSd[ch0+j]);
        Pv[j] = P;
        float q = sH[(ch0+j)*17 + n];
        b = fmaf(P, b, q);
        a = a * P;
    }

    #pragma unroll
    for (int o=1; o<32; o<<=1){
        float ap = __shfl_up_sync(0xffffffffu, a, o);
        float bp = __shfl_up_sync(0xffffffffu, b, o);
        if (g >= o){
            b = fmaf(a, bp, b);
            a = a * ap;
        }
    }
    float bex = __shfl_up_sync(0xffffffffu, b, 1);
    float h = (g == 0) ? 0.f : bex;

    #pragma unroll
    for (int j=0; j<CPT; j++){
        float q = sH[(ch0+j)*17 + n];
        sH[(ch0+j)*17 + n] = h;
        h = fmaf(Pv[j], h, q);
    }
    __syncthreads();

    float4* dst4 = (float4*)(g_H + (size_t)kd*NC*16);
    for (int i=tid; i<NC*4; i+=512){
        int e = i*4; int ch = e>>4, nn = e&15;
        const float* p = &sH[ch*17+nn];
        dst4[i] = make_float4(p[0], p[1], p[2], p[3]);
    }
}

// ---------------------------------------------------------------------------
// Pass 3: correction (no recurrence). ONE thread per (chunk, d) with all 16
// states — no duplicated loads, no shfl. 192 threads = 2 chunks x 96 d.
// ---------------------------------------------------------------------------
template<int KI>
__device__ __forceinline__ void scan3_body(const float* __restrict__ A_logs,
                                           const float* __restrict__ Cs_s,
                                           int chb){
    int tid = threadIdx.x;
    int sub = tid / 96;          // chunk within block
    int d   = tid - sub*96;
    int ch  = chb*2 + sub;
    int c0  = ch*LC;
    int kd  = KI*96 + d;

    u64 Ap[8];
    #pragma unroll
    for (int p=0;p<8;p++){
        float a0 = -__expf(A_logs[kd*NN + 2*p  ]) * LOG2E;
        float a1 = -__expf(A_logs[kd*NN + 2*p+1]) * LOG2E;
        Ap[p] = pack2(a0, a1);
    }
    const float4* hp4 = (const float4*)&g_H[((size_t)kd*NC + ch)*16];
    float4 h0=hp4[0], h1=hp4[1], h2=hp4[2], h3=hp4[3];
    u64 Hp[8] = { pack2(h0.x,h0.y), pack2(h0.z,h0.w),
                  pack2(h1.x,h1.y), pack2(h1.z,h1.w),
                  pack2(h2.x,h2.y), pack2(h2.z,h2.w),
                  pack2(h3.x,h3.y), pack2(h3.z,h3.w) };

    constexpr int PSTEP = (KI==0) ? 96 : (KI==2) ? -96 : (KI==1) ? 9216 : -9216;
    int slot0;
    if      (KI == 0) slot0 = c0;
    else if (KI == 2) slot0 = LL-1-c0;
    else if (KI == 1){ int rr = c0/96; slot0 = (c0 - rr*96)*96 + rr; }
    else             { int lm = LL-1-c0; int rr = lm/96; slot0 = (lm - rr*96)*96 + rr; }

    const float2* dxp = g_dx + ((size_t)KI*LL + c0)*96 + d;
    float*        pp  = g_y  + (size_t)KI*LL*96 + (size_t)slot0*96 + d;
    const float*  cs  = &Cs_s[sub*LC*16];

    #pragma unroll
    for (int li=0; li<LC; li++){
        float2 sv = dxp[li*96];          // (S_cum, y_local + x*Ds)
        u64 Sp = pack2(sv.x, sv.x);
        const float4* cp = (const float4*)&cs[li*16];
        float4 q0=cp[0], q1=cp[1], q2=cp[2], q3=cp[3];
        u64 C[8] = { pack2(q0.x,q0.y), pack2(q0.z,q0.w),
                     pack2(q1.x,q1.y), pack2(q1.z,q1.w),
                     pack2(q2.x,q2.y), pack2(q2.z,q2.w),
                     pack2(q3.x,q3.y), pack2(q3.z,q3.w) };
        u64 Y[4];
        #pragma unroll
        for (int p=0;p<8;p++){
            u64 t = mul2(Sp, Ap[p]);
            float a, b; unpack2(t, a, b);
            u64 e = pack2(ex2f(a), ex2f(b));
            u64 u = mul2(e, Hp[p]);
            if (p < 4) Y[p]   = mul2(u, C[p]);
            else       Y[p-4] = fma2(u, C[p], Y[p-4]);
        }
        u64 Ys = add2(add2(Y[0],Y[1]), add2(Y[2],Y[3]));
        float ya, yb; unpack2(Ys, ya, yb);
        pp[li*PSTEP] = sv.y + (ya + yb);
    }
}

__global__ __launch_bounds__(192) void k_scan3(const float* __restrict__ A_logs){
    __shared__ float Cs_s[2*LC*16];
    int k   = blockIdx.y;
    int chb = blockIdx.x;
    int tid = threadIdx.x;

    for (int idx=tid; idx<2*LC*16; idx+=192)
        Cs_s[idx] = g_BC[((size_t)k*LL + chb*32)*16 + idx];
    __syncthreads();

    switch(k){
        case 0: scan3_body<0>(A_logs, Cs_s, chb); break;
        case 1: scan3_body<1>(A_logs, Cs_s, chb); break;
        case 2: scan3_body<2>(A_logs, Cs_s, chb); break;
        default: scan3_body<3>(A_logs, Cs_s, chb); break;
    }
}

// ---------------------------------------------------------------------------
// Final: warp per output row l; lanes 0..23 own 4 d-values (float4).
// ---------------------------------------------------------------------------
__global__ __launch_bounds__(256) void k_final(const float* __restrict__ lnw,
                                               const float* __restrict__ lnb,
                                               float* __restrict__ out){
    int lane = threadIdx.x & 31;
    int wrp  = threadIdx.x >> 5;
    int l    = blockIdx.x*8 + wrp;

    float4 v = make_float4(0.f,0.f,0.f,0.f);
    size_t base = (size_t)l*96 + lane*4;
    if (lane < 24){
        const float4* p0 = (const float4*)(g_y + base);
        const float4* p1 = (const float4*)(g_y + (size_t)1*LL*96 + base);
        const float4* p2 = (const float4*)(g_y + (size_t)2*LL*96 + base);
        const float4* p3 = (const float4*)(g_y + (size_t)3*LL*96 + base);
        float4 a = p0[0], b = p1[0], c = p2[0], e = p3[0];
        v.x = (a.x+b.x)+(c.x+e.x);
        v.y = (a.y+b.y)+(c.y+e.y);
        v.z = (a.z+b.z)+(c.z+e.z);
        v.w = (a.w+b.w)+(c.w+e.w);
    }
    float s  = (v.x+v.y)+(v.z+v.w);
    float ss = (v.x*v.x+v.y*v.y)+(v.z*v.z+v.w*v.w);
    #pragma unroll
    for (int o=16;o>0;o>>=1){
        s  += __shfl_xor_sync(0xffffffffu, s,  o);
        ss += __shfl_xor_sync(0xffffffffu, ss, o);
    }
    float mu  = s*(1.f/96.f);
    float var = fmaxf(ss*(1.f/96.f) - mu*mu, 0.f);
    float rr  = rsqrtf(var + 1e-5f);
    if (lane < 24){
        float4 w = *(const float4*)(lnw + lane*4);
        float4 b = *(const float4*)(lnb + lane*4);
        float4 o4;
        o4.x = (v.x-mu)*rr*w.x + b.x;
        o4.y = (v.y-mu)*rr*w.y + b.y;
        o4.z = (v.z-mu)*rr*w.z + b.z;
        o4.w = (v.w-mu)*rr*w.w + b.w;
        *(float4*)(out + base) = o4;
    }
}

// ---------------------------------------------------------------------------
extern "C" void kernel_launch(void* const* d_in, const int* in_sizes, int n_in,
                              void* d_out, int out_size)
{
    const float* x   = (const float*)d_in[0];
    const float* W   = (const float*)d_in[1];
    const float* dtw = (const float*)d_in[2];
    const float* dtb = (const float*)d_in[3];
    const float* Al  = (const float*)d_in[4];
    const float* Ds  = (const float*)d_in[5];
    const float* lnw = (const float*)d_in[6];
    const float* lnb = (const float*)d_in[7];
    float* out = (float*)d_out;

    k_transpose<<<dim3(3,3,96), dim3(32,8)>>>(x);
    k_proj     <<<dim3(LL/32, KK), 384>>>(x, W, dtw, dtb, Al, Ds);
    k_scan2    <<<KD, 512>>>(Al);
    k_scan3    <<<dim3(NC/2, KK), 192>>>(Al);
    k_final    <<<LL/8, 256>>>(lnw, lnb, out);
}

// round 16
// speedup vs baseline: 1.0767x; 1.0767x over previous
#include <cuda_runtime.h>
#include <math.h>

#define DD 96
#define LL 9216
#define KK 4
#define NN 16
#define RR 6
#define CC 38
#define LC 16
#define NC 576   // LL/LC
#define KD 384   // KK*DD
#define LOG2E 1.4426950408889634f
#define LN2   0.6931471805599453f

typedef unsigned long long u64;

__device__ __forceinline__ float ex2f(float x){
    float y; asm("ex2.approx.f32 %0, %1;" : "=f"(y) : "f"(x)); return y;
}
__device__ __forceinline__ float lg2f(float x){
    float y; asm("lg2.approx.f32 %0, %1;" : "=f"(y) : "f"(x)); return y;
}
// packed f32x2 helpers (sm_100+)
__device__ __forceinline__ u64 pack2(float lo, float hi){
    u64 r; asm("mov.b64 %0, {%1,%2};" : "=l"(r) : "f"(lo), "f"(hi)); return r;
}
__device__ __forceinline__ void unpack2(u64 v, float& lo, float& hi){
    asm("mov.b64 {%0,%1}, %2;" : "=f"(lo), "=f"(hi) : "l"(v));
}
__device__ __forceinline__ u64 mul2(u64 a, u64 b){
    u64 r; asm("mul.rn.f32x2 %0, %1, %2;" : "=l"(r) : "l"(a), "l"(b)); return r;
}
__device__ __forceinline__ u64 fma2(u64 a, u64 b, u64 c){
    u64 r; asm("fma.rn.f32x2 %0, %1, %2, %3;" : "=l"(r) : "l"(a), "l"(b), "l"(c)); return r;
}
__device__ __forceinline__ u64 add2(u64 a, u64 b){
    u64 r; asm("add.rn.f32x2 %0, %1, %2;" : "=l"(r) : "l"(a), "l"(b)); return r;
}
__device__ __forceinline__ float softplusf(float x){
    if (x > 20.f) return x;
    float t = ex2f(x * LOG2E);            // e^x
    return lg2f(1.f + t) * LN2;           // ln(1+e^x)
}

// scratch (no allocations allowed)
__device__ float  g_xT[DD*LL];          // transposed image per d
__device__ float  g_BC[KK*LL*16];       // (k,l,[C0..15])  (C only)
__device__ float2 g_dx[KK*LL*DD];       // (k,l,d) -> (S_cum, y_local + x*Ds)
__device__ float  g_Sd[KD*NC];          // [kd][ch]
__device__ float  g_H [KD*NC*NN];       // [kd][ch][n] chunk h (pass1) then h_in (pass2)
__device__ float  g_y [KK*LL*DD];       // 4 planes, aligned to output index l

// ---------------------------------------------------------------------------
// Kernel T: per-d HW transpose of x
// ---------------------------------------------------------------------------
__global__ void k_transpose(const float* __restrict__ x){
    __shared__ float tile[32][33];
    int d  = blockIdx.z;
    int h0 = blockIdx.x*32, w0 = blockIdx.y*32;
    int tx = threadIdx.x,  ty = threadIdx.y;
    const float* xp = x    + (size_t)d*LL;
    float*       op = g_xT + (size_t)d*LL;
    #pragma unroll
    for (int i=0;i<4;i++) tile[ty+8*i][tx] = xp[(h0+ty+8*i)*96 + w0+tx];
    __syncthreads();
    #pragma unroll
    for (int i=0;i<4;i++) op[(w0+ty+8*i)*96 + h0+tx] = tile[tx][ty+8*i];
}

// ---------------------------------------------------------------------------
// Kernel A (fused): projections + chunk-local scan (f32x2) with local output.
// dbl_s is li-major, 48-float segmented rows: [dts 0..5 | pad | B 8..23 | C 24..39]
// -> scan phase loads B/C as LDS.128 broadcasts.
// ---------------------------------------------------------------------------
__global__ __launch_bounds__(384) void k_proj(
    const float* __restrict__ x,  const float* __restrict__ W,
    const float* __restrict__ dtw,const float* __restrict__ dtb,
    const float* __restrict__ A_logs, const float* __restrict__ Ds)
{
    __shared__ float xs_s [96*33];
    __shared__ float Wt_s [96*40];   // reused as delta_s after GEMM
    __shared__ float dbl_s[32*48];   // [li][slot]
    __shared__ float Wdt_s[96*6];
    __shared__ float bias_s[96];

    int k   = blockIdx.y;
    int l0  = blockIdx.x*32;
    int tid = threadIdx.x;
    const float* src = (k & 1) ? g_xT : x;

    for (int idx=tid; idx<96*32; idx+=384){
        int d = idx>>5, li = idx&31;
        int l = l0+li;
        int ls = (k<2) ? l : (LL-1-l);
        xs_s[d*33+li] = src[(size_t)d*LL + ls];
    }
    for (int idx=tid; idx<CC*96; idx+=384){
        int c = idx/96, d = idx - c*96;
        Wt_s[d*40+c] = W[(k*CC+c)*96 + d];
    }
    for (int idx=tid; idx<96*6; idx+=384) Wdt_s[idx] = dtw[k*576 + idx];
    if (tid < 96) bias_s[tid] = dtb[k*96 + tid];
    __syncthreads();

    int lane = tid & 31, wrp = tid >> 5;
    if (wrp < 10){
        int c0 = wrp*4;
        float ax=0.f, ay=0.f, az=0.f, aw=0.f;
        for (int d=0; d<96; d++){
            float  xv = xs_s[d*33+lane];
            float4 wv = *(const float4*)&Wt_s[d*40+c0];
            ax = fmaf(wv.x, xv, ax); ay = fmaf(wv.y, xv, ay);
            az = fmaf(wv.z, xv, az); aw = fmaf(wv.w, xv, aw);
        }
        int s0 = c0   + ((c0  >=6) ? 2 : 0);
        int s1 = c0+1 + ((c0+1>=6) ? 2 : 0);
        int s2 = c0+2 + ((c0+2>=6) ? 2 : 0);
        int s3 = c0+3 + ((c0+3>=6) ? 2 : 0);
        dbl_s[lane*48 + s0] = ax;
        dbl_s[lane*48 + s1] = ay;
        dbl_s[lane*48 + s2] = az;
        dbl_s[lane*48 + s3] = aw;
    }
    __syncthreads();   // GEMM done; Wt_s dead -> reuse as delta_s

    float* delta_s = Wt_s;

    // C out (slots 24..39)
    for (int idx=tid; idx<32*16; idx+=384){
        int li = idx>>4, j = idx&15;
        g_BC[((size_t)k*LL + l0+li)*16 + j] = dbl_s[li*48 + 24 + j];
    }
    // delta (fast softplus); dts at slots 0..5
    for (int idx=tid; idx<96*32; idx+=384){
        int d = idx%96, li = idx/96;
        float4 r03 = *(const float4*)&dbl_s[li*48];
        float2 r45 = *(const float2*)&dbl_s[li*48 + 4];
        float acc = bias_s[d];
        acc = fmaf(r03.x, Wdt_s[d*6+0], acc);
        acc = fmaf(r03.y, Wdt_s[d*6+1], acc);
        acc = fmaf(r03.z, Wdt_s[d*6+2], acc);
        acc = fmaf(r03.w, Wdt_s[d*6+3], acc);
        acc = fmaf(r45.x, Wdt_s[d*6+4], acc);
        acc = fmaf(r45.y, Wdt_s[d*6+5], acc);
        delta_s[d*33+li] = softplusf(acc);
    }
    __syncthreads();

    // fused chunk-local scan (f32x2), n-split
    {
        int sub = tid / 192;
        int r   = tid - sub*192;
        int d   = r >> 1;
        int nh  = r & 1;
        int kd  = k*96 + d;
        int ch  = blockIdx.x*2 + sub;
        int lb  = sub*16;
        int nb  = nh*8;

        float Aa2[8];
        #pragma unroll
        for (int j=0;j<8;j++) Aa2[j] = -__expf(A_logs[kd*NN + nb + j]) * LOG2E;
        u64 Ap[4];
        #pragma unroll
        for (int p=0;p<4;p++) Ap[p] = pack2(Aa2[2*p], Aa2[2*p+1]);
        u64 Hp[4];
        #pragma unroll
        for (int p=0;p<4;p++) Hp[p] = pack2(0.f, 0.f);
        float sd = 0.f;
        float Dsv = Ds[kd];
        float2* dxw = g_dx + ((size_t)k*LL + l0 + lb)*96 + d;

        #pragma unroll
        for (int i=0; i<LC; i++){
            int li = lb + i;
            float delta = delta_s[d*33+li];
            float xv    = xs_s[d*33+li];
            float du    = delta * xv;
            sd += delta;
            u64 Dp  = pack2(delta, delta);
            u64 DUp = pack2(du, du);
            // B/C as float4 broadcasts from the segmented row
            float4 B01 = *(const float4*)&dbl_s[li*48 + 8  + nb];
            float4 B23 = *(const float4*)&dbl_s[li*48 + 12 + nb];
            float4 C01 = *(const float4*)&dbl_s[li*48 + 24 + nb];
            float4 C23 = *(const float4*)&dbl_s[li*48 + 28 + nb];
            u64 Bp[4] = { pack2(B01.x,B01.y), pack2(B01.z,B01.w),
                          pack2(B23.x,B23.y), pack2(B23.z,B23.w) };
            u64 Cp[4] = { pack2(C01.x,C01.y), pack2(C01.z,C01.w),
                          pack2(C23.x,C23.y), pack2(C23.z,C23.w) };
            #pragma unroll
            for (int p=0; p<4; p++){
                u64 t = mul2(Dp, Ap[p]);
                float a, b; unpack2(t, a, b);
                u64 e = pack2(ex2f(a), ex2f(b));
                Hp[p] = fma2(Hp[p], e, mul2(DUp, Bp[p]));
            }
            u64 Ya = mul2(Hp[0], Cp[0]); Ya = fma2(Hp[1], Cp[1], Ya);
            u64 Yb = mul2(Hp[2], Cp[2]); Yb = fma2(Hp[3], Cp[3], Yb);
            u64 Ys = add2(Ya, Yb);
            float ya, yb; unpack2(Ys, ya, yb);
            float y = ya + yb;
            y += __shfl_xor_sync(0xffffffffu, y, 1);
            if (nh == 0) dxw[(size_t)i*96] = make_float2(sd, y + xv*Dsv);
        }
        if (nh == 0) g_Sd[(size_t)kd*NC + ch] = sd;
        float h0,h1,h2,h3,h4,h5,h6,h7;
        unpack2(Hp[0],h0,h1); unpack2(Hp[1],h2,h3);
        unpack2(Hp[2],h4,h5); unpack2(Hp[3],h6,h7);
        float4* hp = (float4*)&g_H[((size_t)kd*NC + ch)*16 + nb];
        hp[0] = make_float4(h0,h1,h2,h3);
        hp[1] = make_float4(h4,h5,h6,h7);
    }
}

// ---------------------------------------------------------------------------
// Pass 2: parallel chunk-combine. One block per (k,d) sequence.
// ---------------------------------------------------------------------------
#define CPT 18
__global__ __launch_bounds__(512) void k_scan2(const float* __restrict__ A_logs){
    __shared__ float sH [NC*17];
    __shared__ float sSd[NC];

    int kd  = blockIdx.x;
    int tid = threadIdx.x;

    const float4* src4 = (const float4*)(g_H + (size_t)kd*NC*16);
    for (int i=tid; i<NC*4; i+=512){
        float4 v = src4[i];
        int e = i*4; int ch = e>>4, n = e&15;
        float* p = &sH[ch*17+n];
        p[0]=v.x; p[1]=v.y; p[2]=v.z; p[3]=v.w;
    }
    const float4* sd4 = (const float4*)(g_Sd + (size_t)kd*NC);
    for (int i=tid; i<NC/4; i+=512){
        float4 v = sd4[i];
        sSd[i*4+0]=v.x; sSd[i*4+1]=v.y; sSd[i*4+2]=v.z; sSd[i*4+3]=v.w;
    }
    __syncthreads();

    int n = tid >> 5;
    int g = tid & 31;
    float Av2 = -__expf(A_logs[kd*16 + n]) * LOG2E;
    int ch0 = g*CPT;

    float Pv[CPT];
    float a = 1.f, b = 0.f;
    #pragma unroll
    for (int j=0; j<CPT; j++){
        float P = ex2f(Av2 * sSd[ch0+j]);
        Pv[j] = P;
        float q = sH[(ch0+j)*17 + n];
        b = fmaf(P, b, q);
        a = a * P;
    }

    #pragma unroll
    for (int o=1; o<32; o<<=1){
        float ap = __shfl_up_sync(0xffffffffu, a, o);
        float bp = __shfl_up_sync(0xffffffffu, b, o);
        if (g >= o){
            b = fmaf(a, bp, b);
            a = a * ap;
        }
    }
    float bex = __shfl_up_sync(0xffffffffu, b, 1);
    float h = (g == 0) ? 0.f : bex;

    #pragma unroll
    for (int j=0; j<CPT; j++){
        float q = sH[(ch0+j)*17 + n];
        sH[(ch0+j)*17 + n] = h;
        h = fmaf(Pv[j], h, q);
    }
    __syncthreads();

    float4* dst4 = (float4*)(g_H + (size_t)kd*NC*16);
    for (int i=tid; i<NC*4; i+=512){
        int e = i*4; int ch = e>>4, nn = e&15;
        const float* p = &sH[ch*17+nn];
        dst4[i] = make_float4(p[0], p[1], p[2], p[3]);
    }
}

// ---------------------------------------------------------------------------
// Pass 3: correction (no recurrence), f32x2 packed, n-split (R13 config).
//   y(l) = y_local(l) + sum_n C_n(l) * ex2(A_n*S(l)) * h_in[n]
// ---------------------------------------------------------------------------
template<int KI>
__device__ __forceinline__ void scan3_body(const float* __restrict__ A_logs,
                                           const float* __restrict__ Cs_s,
                                           int chb){
    int tid = threadIdx.x;
    int sub = tid / 192;
    int r   = tid - sub*192;
    int d   = r >> 1;
    int nh  = r & 1;
    int ch  = chb*2 + sub;
    int c0  = ch*LC;

    int kd = KI*96 + d;
    int nb = nh*8;
    float Aa2[8];
    #pragma unroll
    for (int j=0;j<8;j++) Aa2[j] = -__expf(A_logs[kd*NN + nb + j]) * LOG2E;
    u64 Ap[4];
    #pragma unroll
    for (int p=0;p<4;p++) Ap[p] = pack2(Aa2[2*p], Aa2[2*p+1]);

    const float4* hp = (const float4*)&g_H[((size_t)kd*NC + ch)*16 + nb];
    float4 h0v=hp[0], h1v=hp[1];
    u64 Hp[4] = { pack2(h0v.x,h0v.y), pack2(h0v.z,h0v.w),
                  pack2(h1v.x,h1v.y), pack2(h1v.z,h1v.w) };

    constexpr int PSTEP = (KI==0) ? 96 : (KI==2) ? -96 : (KI==1) ? 9216 : -9216;
    int slot0;
    if      (KI == 0) slot0 = c0;
    else if (KI == 2) slot0 = LL-1-c0;
    else if (KI == 1){ int rr = c0/96; slot0 = (c0 - rr*96)*96 + rr; }
    else             { int lm = LL-1-c0; int rr = lm/96; slot0 = (lm - rr*96)*96 + rr; }

    const float2* dxp = g_dx + ((size_t)KI*LL + c0)*96 + d;
    float*        pp  = g_y  + (size_t)KI*LL*96 + (size_t)slot0*96 + d;
    const float*  cs  = &Cs_s[sub*LC*16 + nb];

    #pragma unroll
    for (int li=0; li<LC; li++){
        float2 sv = dxp[li*96];          // (S_cum, y_local + x*Ds)
        u64 Sp = pack2(sv.x, sv.x);
        const float4* cp = (const float4*)&cs[li*16];
        float4 q0 = cp[0], q1 = cp[1];
        u64 C0 = pack2(q0.x,q0.y), C1 = pack2(q0.z,q0.w);
        u64 C2 = pack2(q1.x,q1.y), C3 = pack2(q1.z,q1.w);
        u64 t0 = mul2(Sp, Ap[0]), t1 = mul2(Sp, Ap[1]);
        u64 t2 = mul2(Sp, Ap[2]), t3 = mul2(Sp, Ap[3]);
        float a0,b0,a1,b1,a2,b2,a3,b3;
        unpack2(t0,a0,b0); unpack2(t1,a1,b1);
        unpack2(t2,a2,b2); unpack2(t3,a3,b3);
        u64 p0 = pack2(ex2f(a0), ex2f(b0));
        u64 p1 = pack2(ex2f(a1), ex2f(b1));
        u64 p2 = pack2(ex2f(a2), ex2f(b2));
        u64 p3 = pack2(ex2f(a3), ex2f(b3));
        u64 u0 = mul2(p0, Hp[0]), u1 = mul2(p1, Hp[1]);
        u64 u2 = mul2(p2, Hp[2]), u3 = mul2(p3, Hp[3]);
        u64 Ya = mul2(u0, C0); Ya = fma2(u1, C1, Ya);
        u64 Yb = mul2(u2, C2); Yb = fma2(u3, C3, Yb);
        u64 Ys = add2(Ya, Yb);
        float ya, yb; unpack2(Ys, ya, yb);
        float y = ya + yb;
        y += __shfl_xor_sync(0xffffffffu, y, 1);
        if (nh == 0) pp[li*PSTEP] = sv.y + y;
    }
}

__global__ __launch_bounds__(384) void k_scan3(const float* __restrict__ A_logs){
    __shared__ float Cs_s[2*LC*16];
    int k   = blockIdx.y;
    int chb = blockIdx.x;
    int tid = threadIdx.x;

    for (int idx=tid; idx<2*LC*16; idx+=384)
        Cs_s[idx] = g_BC[((size_t)k*LL + chb*32)*16 + idx];
    __syncthreads();

    switch(k){
        case 0: scan3_body<0>(A_logs, Cs_s, chb); break;
        case 1: scan3_body<1>(A_logs, Cs_s, chb); break;
        case 2: scan3_body<2>(A_logs, Cs_s, chb); break;
        default: scan3_body<3>(A_logs, Cs_s, chb); break;
    }
}

// ---------------------------------------------------------------------------
// Final: warp per output row l; lanes 0..23 own 4 d-values (float4).
// ---------------------------------------------------------------------------
__global__ __launch_bounds__(256) void k_final(const float* __restrict__ lnw,
                                               const float* __restrict__ lnb,
                                               float* __restrict__ out){
    int lane = threadIdx.x & 31;
    int wrp  = threadIdx.x >> 5;
    int l    = blockIdx.x*8 + wrp;

    float4 v = make_float4(0.f,0.f,0.f,0.f);
    size_t base = (size_t)l*96 + lane*4;
    if (lane < 24){
        const float4* p0 = (const float4*)(g_y + base);
        const float4* p1 = (const float4*)(g_y + (size_t)1*LL*96 + base);
        const float4* p2 = (const float4*)(g_y + (size_t)2*LL*96 + base);
        const float4* p3 = (const float4*)(g_y + (size_t)3*LL*96 + base);
        float4 a = p0[0], b = p1[0], c = p2[0], e = p3[0];
        v.x = (a.x+b.x)+(c.x+e.x);
        v.y = (a.y+b.y)+(c.y+e.y);
        v.z = (a.z+b.z)+(c.z+e.z);
        v.w = (a.w+b.w)+(c.w+e.w);
    }
    float s  = (v.x+v.y)+(v.z+v.w);
    float ss = (v.x*v.x+v.y*v.y)+(v.z*v.z+v.w*v.w);
    #pragma unroll
    for (int o=16;o>0;o>>=1){
        s  += __shfl_xor_sync(0xffffffffu, s,  o);
        ss += __shfl_xor_sync(0xffffffffu, ss, o);
    }
    float mu  = s*(1.f/96.f);
    float var = fmaxf(ss*(1.f/96.f) - mu*mu, 0.f);
    float rr  = rsqrtf(var + 1e-5f);
    if (lane < 24){
        float4 w = *(const float4*)(lnw + lane*4);
        float4 b = *(const float4*)(lnb + lane*4);
        float4 o4;
        o4.x = (v.x-mu)*rr*w.x + b.x;
        o4.y = (v.y-mu)*rr*w.y + b.y;
        o4.z = (v.z-mu)*rr*w.z + b.z;
        o4.w = (v.w-mu)*rr*w.w + b.w;
        *(float4*)(out + base) = o4;
    }
}

// ---------------------------------------------------------------------------
extern "C" void kernel_launch(void* const* d_in, const int* in_sizes, int n_in,
                              void* d_out, int out_size)
{
    const float* x   = (const float*)d_in[0];
    const float* W   = (const float*)d_in[1];
    const float* dtw = (const float*)d_in[2];
    const float* dtb = (const float*)d_in[3];
    const float* Al  = (const float*)d_in[4];
    const float* Ds  = (const float*)d_in[5];
    const float* lnw = (const float*)d_in[6];
    const float* lnb = (const float*)d_in[7];
    float* out = (float*)d_out;

    k_transpose<<<dim3(3,3,96), dim3(32,8)>>>(x);
    k_proj     <<<dim3(LL/32, KK), 384>>>(x, W, dtw, dtb, Al, Ds);
    k_scan2    <<<KD, 512>>>(Al);
    k_scan3    <<<dim3(NC/2, KK), 384>>>(Al);
    k_final    <<<LL/8, 256>>>(lnw, lnb, out);
}

// round 17
// speedup vs baseline: 1.1268x; 1.0465x over previous
#include <cuda_runtime.h>
#include <math.h>

#define DD 96
#define LL 9216
#define KK 4
#define NN 16
#define RR 6
#define CC 38
#define LC 16
#define NC 576   // LL/LC
#define KD 384   // KK*DD
#define LOG2E 1.4426950408889634f
#define LN2   0.6931471805599453f

typedef unsigned long long u64;

__device__ __forceinline__ float ex2f(float x){
    float y; asm("ex2.approx.f32 %0, %1;" : "=f"(y) : "f"(x)); return y;
}
__device__ __forceinline__ float lg2f(float x){
    float y; asm("lg2.approx.f32 %0, %1;" : "=f"(y) : "f"(x)); return y;
}
// packed f32x2 helpers (sm_100+)
__device__ __forceinline__ u64 pack2(float lo, float hi){
    u64 r; asm("mov.b64 %0, {%1,%2};" : "=l"(r) : "f"(lo), "f"(hi)); return r;
}
__device__ __forceinline__ void unpack2(u64 v, float& lo, float& hi){
    asm("mov.b64 {%0,%1}, %2;" : "=f"(lo), "=f"(hi) : "l"(v));
}
__device__ __forceinline__ u64 mul2(u64 a, u64 b){
    u64 r; asm("mul.rn.f32x2 %0, %1, %2;" : "=l"(r) : "l"(a), "l"(b)); return r;
}
__device__ __forceinline__ u64 fma2(u64 a, u64 b, u64 c){
    u64 r; asm("fma.rn.f32x2 %0, %1, %2, %3;" : "=l"(r) : "l"(a), "l"(b), "l"(c)); return r;
}
__device__ __forceinline__ u64 add2(u64 a, u64 b){
    u64 r; asm("add.rn.f32x2 %0, %1, %2;" : "=l"(r) : "l"(a), "l"(b)); return r;
}
__device__ __forceinline__ float softplusf(float x){
    if (x > 20.f) return x;
    float t = ex2f(x * LOG2E);            // e^x
    return lg2f(1.f + t) * LN2;           // ln(1+e^x)
}

// scratch (no allocations allowed)
__device__ float  g_xT[DD*LL];          // transposed image per d
__device__ float  g_BC[KK*LL*16];       // (k,l,[C0..15])  (C only)
__device__ float2 g_dx[KK*LL*DD];       // (k,l,d) -> (S_cum, y_local + x*Ds)
__device__ float  g_Sd[KD*NC];          // [kd][ch]
__device__ float  g_H [KD*NC*NN];       // [kd][ch][n] chunk h (pass1) then h_in (pass2)
__device__ float  g_y [KK*LL*DD];       // 4 planes, aligned to output index l

// ---------------------------------------------------------------------------
// Kernel T: per-d HW transpose of x
// ---------------------------------------------------------------------------
__global__ void k_transpose(const float* __restrict__ x){
    __shared__ float tile[32][33];
    int d  = blockIdx.z;
    int h0 = blockIdx.x*32, w0 = blockIdx.y*32;
    int tx = threadIdx.x,  ty = threadIdx.y;
    const float* xp = x    + (size_t)d*LL;
    float*       op = g_xT + (size_t)d*LL;
    #pragma unroll
    for (int i=0;i<4;i++) tile[ty+8*i][tx] = xp[(h0+ty+8*i)*96 + w0+tx];
    __syncthreads();
    #pragma unroll
    for (int i=0;i<4;i++) op[(w0+ty+8*i)*96 + h0+tx] = tile[tx][ty+8*i];
}

// ---------------------------------------------------------------------------
// Kernel A (fused): projections + chunk-local scan (f32x2) with local output.
// dbl_s is li-major, 48-float segmented rows: [dts 0..5 | pad | B 8..23 | C 24..39]
// ---------------------------------------------------------------------------
__global__ __launch_bounds__(384) void k_proj(
    const float* __restrict__ x,  const float* __restrict__ W,
    const float* __restrict__ dtw,const float* __restrict__ dtb,
    const float* __restrict__ A_logs, const float* __restrict__ Ds)
{
    __shared__ float xs_s [96*33];
    __shared__ float Wt_s [96*40];   // reused as delta_s after GEMM
    __shared__ float dbl_s[32*48];   // [li][slot]
    __shared__ float Wdt_s[96*6];
    __shared__ float bias_s[96];

    int k   = blockIdx.y;
    int l0  = blockIdx.x*32;
    int tid = threadIdx.x;
    const float* src = (k & 1) ? g_xT : x;

    for (int idx=tid; idx<96*32; idx+=384){
        int d = idx>>5, li = idx&31;
        int l = l0+li;
        int ls = (k<2) ? l : (LL-1-l);
        xs_s[d*33+li] = src[(size_t)d*LL + ls];
    }
    for (int idx=tid; idx<CC*96; idx+=384){
        int c = idx/96, d = idx - c*96;
        Wt_s[d*40+c] = W[(k*CC+c)*96 + d];
    }
    for (int idx=tid; idx<96*6; idx+=384) Wdt_s[idx] = dtw[k*576 + idx];
    if (tid < 96) bias_s[tid] = dtb[k*96 + tid];
    __syncthreads();

    int lane = tid & 31, wrp = tid >> 5;
    if (wrp < 10){
        int c0 = wrp*4;
        float ax=0.f, ay=0.f, az=0.f, aw=0.f;
        for (int d=0; d<96; d++){
            float  xv = xs_s[d*33+lane];
            float4 wv = *(const float4*)&Wt_s[d*40+c0];
            ax = fmaf(wv.x, xv, ax); ay = fmaf(wv.y, xv, ay);
            az = fmaf(wv.z, xv, az); aw = fmaf(wv.w, xv, aw);
        }
        int s0 = c0   + ((c0  >=6) ? 2 : 0);
        int s1 = c0+1 + ((c0+1>=6) ? 2 : 0);
        int s2 = c0+2 + ((c0+2>=6) ? 2 : 0);
        int s3 = c0+3 + ((c0+3>=6) ? 2 : 0);
        dbl_s[lane*48 + s0] = ax;
        dbl_s[lane*48 + s1] = ay;
        dbl_s[lane*48 + s2] = az;
        dbl_s[lane*48 + s3] = aw;
    }
    __syncthreads();   // GEMM done; Wt_s dead -> reuse as delta_s

    float* delta_s = Wt_s;

    // C out (slots 24..39)
    for (int idx=tid; idx<32*16; idx+=384){
        int li = idx>>4, j = idx&15;
        g_BC[((size_t)k*LL + l0+li)*16 + j] = dbl_s[li*48 + 24 + j];
    }
    // delta (fast softplus); dts at slots 0..5
    for (int idx=tid; idx<96*32; idx+=384){
        int d = idx%96, li = idx/96;
        float4 r03 = *(const float4*)&dbl_s[li*48];
        float2 r45 = *(const float2*)&dbl_s[li*48 + 4];
        float acc = bias_s[d];
        acc = fmaf(r03.x, Wdt_s[d*6+0], acc);
        acc = fmaf(r03.y, Wdt_s[d*6+1], acc);
        acc = fmaf(r03.z, Wdt_s[d*6+2], acc);
        acc = fmaf(r03.w, Wdt_s[d*6+3], acc);
        acc = fmaf(r45.x, Wdt_s[d*6+4], acc);
        acc = fmaf(r45.y, Wdt_s[d*6+5], acc);
        delta_s[d*33+li] = softplusf(acc);
    }
    __syncthreads();

    // fused chunk-local scan (f32x2), n-split
    {
        int sub = tid / 192;
        int r   = tid - sub*192;
        int d   = r >> 1;
        int nh  = r & 1;
        int kd  = k*96 + d;
        int ch  = blockIdx.x*2 + sub;
        int lb  = sub*16;
        int nb  = nh*8;

        float Aa2[8];
        #pragma unroll
        for (int j=0;j<8;j++) Aa2[j] = -__expf(A_logs[kd*NN + nb + j]) * LOG2E;
        u64 Ap[4];
        #pragma unroll
        for (int p=0;p<4;p++) Ap[p] = pack2(Aa2[2*p], Aa2[2*p+1]);
        u64 Hp[4];
        #pragma unroll
        for (int p=0;p<4;p++) Hp[p] = pack2(0.f, 0.f);
        float sd = 0.f;
        float Dsv = Ds[kd];
        float2* dxw = g_dx + ((size_t)k*LL + l0 + lb)*96 + d;

        #pragma unroll
        for (int i=0; i<LC; i++){
            int li = lb + i;
            float delta = delta_s[d*33+li];
            float xv    = xs_s[d*33+li];
            float du    = delta * xv;
            sd += delta;
            u64 Dp  = pack2(delta, delta);
            u64 DUp = pack2(du, du);
            float4 B01 = *(const float4*)&dbl_s[li*48 + 8  + nb];
            float4 B23 = *(const float4*)&dbl_s[li*48 + 12 + nb];
            float4 C01 = *(const float4*)&dbl_s[li*48 + 24 + nb];
            float4 C23 = *(const float4*)&dbl_s[li*48 + 28 + nb];
            u64 Bp[4] = { pack2(B01.x,B01.y), pack2(B01.z,B01.w),
                          pack2(B23.x,B23.y), pack2(B23.z,B23.w) };
            u64 Cp[4] = { pack2(C01.x,C01.y), pack2(C01.z,C01.w),
                          pack2(C23.x,C23.y), pack2(C23.z,C23.w) };
            #pragma unroll
            for (int p=0; p<4; p++){
                u64 t = mul2(Dp, Ap[p]);
                float a, b; unpack2(t, a, b);
                u64 e = pack2(ex2f(a), ex2f(b));
                Hp[p] = fma2(Hp[p], e, mul2(DUp, Bp[p]));
            }
            u64 Ya = mul2(Hp[0], Cp[0]); Ya = fma2(Hp[1], Cp[1], Ya);
            u64 Yb = mul2(Hp[2], Cp[2]); Yb = fma2(Hp[3], Cp[3], Yb);
            u64 Ys = add2(Ya, Yb);
            float ya, yb; unpack2(Ys, ya, yb);
            float y = ya + yb;
            y += __shfl_xor_sync(0xffffffffu, y, 1);
            if (nh == 0) dxw[(size_t)i*96] = make_float2(sd, y + xv*Dsv);
        }
        if (nh == 0) g_Sd[(size_t)kd*NC + ch] = sd;
        float h0,h1,h2,h3,h4,h5,h6,h7;
        unpack2(Hp[0],h0,h1); unpack2(Hp[1],h2,h3);
        unpack2(Hp[2],h4,h5); unpack2(Hp[3],h6,h7);
        float4* hp = (float4*)&g_H[((size_t)kd*NC + ch)*16 + nb];
        hp[0] = make_float4(h0,h1,h2,h3);
        hp[1] = make_float4(h4,h5,h6,h7);
    }
}

// ---------------------------------------------------------------------------
// Pass 2: parallel chunk-combine. One block per (k,d) sequence.
// ---------------------------------------------------------------------------
#define CPT 18
__global__ __launch_bounds__(512) void k_scan2(const float* __restrict__ A_logs){
    __shared__ float sH [NC*17];
    __shared__ float sSd[NC];

    int kd  = blockIdx.x;
    int tid = threadIdx.x;

    const float4* src4 = (const float4*)(g_H + (size_t)kd*NC*16);
    for (int i=tid; i<NC*4; i+=512){
        float4 v = src4[i];
        int e = i*4; int ch = e>>4, n = e&15;
        float* p = &sH[ch*17+n];
        p[0]=v.x; p[1]=v.y; p[2]=v.z; p[3]=v.w;
    }
    const float4* sd4 = (const float4*)(g_Sd + (size_t)kd*NC);
    for (int i=tid; i<NC/4; i+=512){
        float4 v = sd4[i];
        sSd[i*4+0]=v.x; sSd[i*4+1]=v.y; sSd[i*4+2]=v.z; sSd[i*4+3]=v.w;
    }
    __syncthreads();

    int n = tid >> 5;
    int g = tid & 31;
    float Av2 = -__expf(A_logs[kd*16 + n]) * LOG2E;
    int ch0 = g*CPT;

    float Pv[CPT];
    float a = 1.f, b = 0.f;
    #pragma unroll
    for (int j=0; j<CPT; j++){
        float P = ex2f(Av2 * sSd[ch0+j]);
        Pv[j] = P;
        float q = sH[(ch0+j)*17 + n];
        b = fmaf(P, b, q);
        a = a * P;
    }

    #pragma unroll
    for (int o=1; o<32; o<<=1){
        float ap = __shfl_up_sync(0xffffffffu, a, o);
        float bp = __shfl_up_sync(0xffffffffu, b, o);
        if (g >= o){
            b = fmaf(a, bp, b);
            a = a * ap;
        }
    }
    float bex = __shfl_up_sync(0xffffffffu, b, 1);
    float h = (g == 0) ? 0.f : bex;

    #pragma unroll
    for (int j=0; j<CPT; j++){
        float q = sH[(ch0+j)*17 + n];
        sH[(ch0+j)*17 + n] = h;
        h = fmaf(Pv[j], h, q);
    }
    __syncthreads();

    float4* dst4 = (float4*)(g_H + (size_t)kd*NC*16);
    for (int i=tid; i<NC*4; i+=512){
        int e = i*4; int ch = e>>4, nn = e&15;
        const float* p = &sH[ch*17+nn];
        dst4[i] = make_float4(p[0], p[1], p[2], p[3]);
    }
}

// ---------------------------------------------------------------------------
// Pass 3: correction (no recurrence), f32x2 packed, n-split.
// NEW: whole (S, y_local) slab staged into smem via contiguous float4 copy
// -> inner loop reads LDS (29 cyc) instead of LDG (234+ cyc).
// ---------------------------------------------------------------------------
template<int KI>
__device__ __forceinline__ void scan3_body(const float* __restrict__ A_logs,
                                           const float* __restrict__ Cs_s,
                                           const float2* __restrict__ dx_s,
                                           int chb){
    int tid = threadIdx.x;
    int sub = tid / 192;
    int r   = tid - sub*192;
    int d   = r >> 1;
    int nh  = r & 1;
    int ch  = chb*2 + sub;
    int c0  = ch*LC;

    int kd = KI*96 + d;
    int nb = nh*8;
    float Aa2[8];
    #pragma unroll
    for (int j=0;j<8;j++) Aa2[j] = -__expf(A_logs[kd*NN + nb + j]) * LOG2E;
    u64 Ap[4];
    #pragma unroll
    for (int p=0;p<4;p++) Ap[p] = pack2(Aa2[2*p], Aa2[2*p+1]);

    const float4* hp = (const float4*)&g_H[((size_t)kd*NC + ch)*16 + nb];
    float4 h0v=hp[0], h1v=hp[1];
    u64 Hp[4] = { pack2(h0v.x,h0v.y), pack2(h0v.z,h0v.w),
                  pack2(h1v.x,h1v.y), pack2(h1v.z,h1v.w) };

    constexpr int PSTEP = (KI==0) ? 96 : (KI==2) ? -96 : (KI==1) ? 9216 : -9216;
    int slot0;
    if      (KI == 0) slot0 = c0;
    else if (KI == 2) slot0 = LL-1-c0;
    else if (KI == 1){ int rr = c0/96; slot0 = (c0 - rr*96)*96 + rr; }
    else             { int lm = LL-1-c0; int rr = lm/96; slot0 = (lm - rr*96)*96 + rr; }

    const float2* dxs = dx_s + (sub*16)*96 + d;       // [li*96]
    float*        pp  = g_y  + (size_t)KI*LL*96 + (size_t)slot0*96 + d;
    const float*  cs  = &Cs_s[sub*LC*16 + nb];

    #pragma unroll
    for (int li=0; li<LC; li++){
        float2 sv = dxs[li*96];          // (S_cum, y_local + x*Ds) from smem
        u64 Sp = pack2(sv.x, sv.x);
        const float4* cp = (const float4*)&cs[li*16];
        float4 q0 = cp[0], q1 = cp[1];
        u64 C0 = pack2(q0.x,q0.y), C1 = pack2(q0.z,q0.w);
        u64 C2 = pack2(q1.x,q1.y), C3 = pack2(q1.z,q1.w);
        u64 t0 = mul2(Sp, Ap[0]), t1 = mul2(Sp, Ap[1]);
        u64 t2 = mul2(Sp, Ap[2]), t3 = mul2(Sp, Ap[3]);
        float a0,b0,a1,b1,a2,b2,a3,b3;
        unpack2(t0,a0,b0); unpack2(t1,a1,b1);
        unpack2(t2,a2,b2); unpack2(t3,a3,b3);
        u64 p0 = pack2(ex2f(a0), ex2f(b0));
        u64 p1 = pack2(ex2f(a1), ex2f(b1));
        u64 p2 = pack2(ex2f(a2), ex2f(b2));
        u64 p3 = pack2(ex2f(a3), ex2f(b3));
        u64 u0 = mul2(p0, Hp[0]), u1 = mul2(p1, Hp[1]);
        u64 u2 = mul2(p2, Hp[2]), u3 = mul2(p3, Hp[3]);
        u64 Ya = mul2(u0, C0); Ya = fma2(u1, C1, Ya);
        u64 Yb = mul2(u2, C2); Yb = fma2(u3, C3, Yb);
        u64 Ys = add2(Ya, Yb);
        float ya, yb; unpack2(Ys, ya, yb);
        float y = ya + yb;
        y += __shfl_xor_sync(0xffffffffu, y, 1);
        if (nh == 0) pp[li*PSTEP] = sv.y + y;
    }
}

__global__ __launch_bounds__(384) void k_scan3(const float* __restrict__ A_logs){
    __shared__ float2 dx_s[32*96];     // 24 KB: (S, y_local) slab for 32 l x 96 d
    __shared__ float  Cs_s[2*LC*16];   // 2 KB
    int k   = blockIdx.y;
    int chb = blockIdx.x;
    int tid = threadIdx.x;

    for (int idx=tid; idx<2*LC*16; idx+=384)
        Cs_s[idx] = g_BC[((size_t)k*LL + chb*32)*16 + idx];
    {
        const float4* src = (const float4*)(g_dx + ((size_t)k*LL + chb*32)*96);
        float4* dst = (float4*)dx_s;
        #pragma unroll
        for (int i=tid; i<1536; i+=384) dst[i] = src[i];
    }
    __syncthreads();

    switch(k){
        case 0: scan3_body<0>(A_logs, Cs_s, dx_s, chb); break;
        case 1: scan3_body<1>(A_logs, Cs_s, dx_s, chb); break;
        case 2: scan3_body<2>(A_logs, Cs_s, dx_s, chb); break;
        default: scan3_body<3>(A_logs, Cs_s, dx_s, chb); break;
    }
}

// ---------------------------------------------------------------------------
// Final: warp per output row l; lanes 0..23 own 4 d-values (float4).
// ---------------------------------------------------------------------------
__global__ __launch_bounds__(256) void k_final(const float* __restrict__ lnw,
                                               const float* __restrict__ lnb,
                                               float* __restrict__ out){
    int lane = threadIdx.x & 31;
    int wrp  = threadIdx.x >> 5;
    int l    = blockIdx.x*8 + wrp;

    float4 v = make_float4(0.f,0.f,0.f,0.f);
    size_t base = (size_t)l*96 + lane*4;
    if (lane < 24){
        const float4* p0 = (const float4*)(g_y + base);
        const float4* p1 = (const float4*)(g_y + (size_t)1*LL*96 + base);
        const float4* p2 = (const float4*)(g_y + (size_t)2*LL*96 + base);
        const float4* p3 = (const float4*)(g_y + (size_t)3*LL*96 + base);
        float4 a = p0[0], b = p1[0], c = p2[0], e = p3[0];
        v.x = (a.x+b.x)+(c.x+e.x);
        v.y = (a.y+b.y)+(c.y+e.y);
        v.z = (a.z+b.z)+(c.z+e.z);
        v.w = (a.w+b.w)+(c.w+e.w);
    }
    float s  = (v.x+v.y)+(v.z+v.w);
    float ss = (v.x*v.x+v.y*v.y)+(v.z*v.z+v.w*v.w);
    #pragma unroll
    for (int o=16;o>0;o>>=1){
        s  += __shfl_xor_sync(0xffffffffu, s,  o);
        ss += __shfl_xor_sync(0xffffffffu, ss, o);
    }
    float mu  = s*(1.f/96.f);
    float var = fmaxf(ss*(1.f/96.f) - mu*mu, 0.f);
    float rr  = rsqrtf(var + 1e-5f);
    if (lane < 24){
        float4 w = *(const float4*)(lnw + lane*4);
        float4 b = *(const float4*)(lnb + lane*4);
        float4 o4;
        o4.x = (v.x-mu)*rr*w.x + b.x;
        o4.y = (v.y-mu)*rr*w.y + b.y;
        o4.z = (v.z-mu)*rr*w.z + b.z;
        o4.w = (v.w-mu)*rr*w.w + b.w;
        *(float4*)(out + base) = o4;
    }
}

// ---------------------------------------------------------------------------
extern "C" void kernel_launch(void* const* d_in, const int* in_sizes, int n_in,
                              void* d_out, int out_size)
{
    const float* x   = (const float*)d_in[0];
    const float* W   = (const float*)d_in[1];
    const float* dtw = (const float*)d_in[2];
    const float* dtb = (const float*)d_in[3];
    const float* Al  = (const float*)d_in[4];
    const float* Ds  = (const float*)d_in[5];
    const float* lnw = (const float*)d_in[6];
    const float* lnb = (const float*)d_in[7];
    float* out = (float*)d_out;

    k_transpose<<<dim3(3,3,96), dim3(32,8)>>>(x);
    k_proj     <<<dim3(LL/32, KK), 384>>>(x, W, dtw, dtb, Al, Ds);
    k_scan2    <<<KD, 512>>>(Al);
    k_scan3    <<<dim3(NC/2, KK), 384>>>(Al);
    k_final    <<<LL/8, 256>>>(lnw, lnb, out);
}